// round 14
// baseline (speedup 1.0000x reference)
#include <cuda_runtime.h>
#include <cuda_fp16.h>
#include <cstdint>
#include <cstddef>

#define S_DIM 8192
#define E_DIM 4096
#define H_DIM 32
#define D_DIM 128
#define NTILES 32                          // E_DIM / 128 n-tiles in Q GEMM
#define KSPLIT 4
#define MTILES (S_DIM / 128)               // 64

// ---------------------------------------------------------------------------
// Scratch (static __device__; no allocation allowed)
// ---------------------------------------------------------------------------
__device__ __half g_x [(size_t)S_DIM * E_DIM];
__device__ __half g_wq[(size_t)E_DIM * E_DIM];
__device__ __half g_wv[(size_t)E_DIM * E_DIM];
__device__ __half g_wk[(size_t)D_DIM * E_DIM];
__device__ float  g_bkc[D_DIM];
__device__ float  g_Kc4[(size_t)KSPLIT * S_DIM * D_DIM];   // split-K partials of Kc
__device__ float  g_pal[(size_t)S_DIM * NTILES * H_DIM];   // partial align, [s][ntile][h]
__device__ float  g_Wt [(size_t)S_DIM * H_DIM];
__device__ int    g_ticket[MTILES];                        // per-m-tile arrival counter

// ---------------------------------------------------------------------------
// PTX helpers (sm_80-era: legal under plain sm_103 target)
// ---------------------------------------------------------------------------
__device__ __forceinline__ uint32_t smem_u32(const void* p) {
    uint32_t a;
    asm("{ .reg .u64 t; cvta.to.shared.u64 t, %1; cvt.u32.u64 %0, t; }" : "=r"(a) : "l"(p));
    return a;
}
__device__ __forceinline__ void cp16(uint32_t s, const void* g) {
    asm volatile("cp.async.cg.shared.global [%0], [%1], 16;" :: "r"(s), "l"(g));
}
#define CP_COMMIT() asm volatile("cp.async.commit_group;" ::: "memory")
#define CP_WAIT(n)  asm volatile("cp.async.wait_group %0;" :: "n"(n) : "memory")

__device__ __forceinline__ void ldsm4(uint32_t& r0, uint32_t& r1, uint32_t& r2, uint32_t& r3,
                                      uint32_t a) {
    asm volatile("ldmatrix.sync.aligned.m8n8.x4.shared.b16 {%0,%1,%2,%3}, [%4];"
                 : "=r"(r0), "=r"(r1), "=r"(r2), "=r"(r3) : "r"(a));
}
__device__ __forceinline__ void mma16816(float* c, const uint32_t* a, const uint32_t* b) {
    asm volatile("mma.sync.aligned.m16n8k16.row.col.f32.f16.f16.f32 "
                 "{%0,%1,%2,%3}, {%4,%5,%6,%7}, {%8,%9}, {%0,%1,%2,%3};"
                 : "+f"(c[0]), "+f"(c[1]), "+f"(c[2]), "+f"(c[3])
                 : "r"(a[0]), "r"(a[1]), "r"(a[2]), "r"(a[3]), "r"(b[0]), "r"(b[1]));
}

// ---------------------------------------------------------------------------
// fp32 -> fp16 conversion (vectorized x4)
// ---------------------------------------------------------------------------
__global__ void cvt_kernel(const float4* __restrict__ in, __half2* __restrict__ out, int n4)
{
    int i = blockIdx.x * blockDim.x + threadIdx.x;
    if (i >= n4) return;
    float4 v = in[i];
    out[2 * i]     = __halves2half2(__float2half_rn(v.x), __float2half_rn(v.y));
    out[2 * i + 1] = __halves2half2(__float2half_rn(v.z), __float2half_rn(v.w));
}

// Gather every 32nd row of Wk -> dense fp16 [128,4096], and bk -> bkc
__global__ void gather_wk_kernel(const float* __restrict__ Wk, const float* __restrict__ bk,
                                 __half* __restrict__ o, float* __restrict__ bkc)
{
    int i = blockIdx.x * blockDim.x + threadIdx.x;   // over 131072 float4s
    int r = i >> 10;
    int c4 = i & 1023;
    float4 v = *(const float4*)(Wk + ((size_t)r * H_DIM) * E_DIM + c4 * 4);
    __half2* o2 = (__half2*)(o + (size_t)r * E_DIM + c4 * 4);
    o2[0] = __halves2half2(__float2half_rn(v.x), __float2half_rn(v.y));
    o2[1] = __halves2half2(__float2half_rn(v.z), __float2half_rn(v.w));
    if (i < D_DIM) bkc[i] = bk[i * H_DIM];
}

// ---------------------------------------------------------------------------
// fp16 mma.sync GEMM:  acc = A[M,K] @ B[N,K]^T ; epilogue by MODE:
//   MODE 1: align partials from (acc+bias)*Kc -> g_pal; LAST arriving CTA per
//           m-tile reduces partials + mask + softmax -> g_Wt (threadfence
//           reduction pattern). aux = mask (int*).
//   MODE 2: C = (acc + bias) * wt[m*32+(n&31)]   (V GEMM -> out)
//   MODE 3: split-K Kc partial: C[part] = acc    (Kc GEMM -> g_Kc4, no bias);
//           also zeroes g_ticket for the following MODE-1 launch.
// CTA 128x128, 4 warps 2x2 (warp tile 64x64), KC=64, 3-stage cp.async,
// 2 CTAs/SM, register double-buffered fragments.
// ---------------------------------------------------------------------------
#define KC 64
#define TILE_B 16384                      // 128 rows x 128 bytes
#define STAGE_B (2 * TILE_B)              // A, B
#define N_STAGES 3
#define SMEM_TOTAL (N_STAGES * STAGE_B)   // 96 KB
#define N_CHUNKS (E_DIM / KC)             // 64

__device__ __forceinline__ void load_tile_cp(const char* __restrict__ g, uint32_t sdst, int tid)
{
#pragma unroll
    for (int j = 0; j < 8; ++j) {
        int i = tid + (j << 7);
        int r = i >> 3, seg = i & 7;
        uint32_t off = (uint32_t)((r << 7) + (((seg ^ (r & 7))) << 4));
        cp16(sdst + off, g + (size_t)r * (E_DIM * 2) + (seg << 4));
    }
}

__device__ __forceinline__ void load_stage(const char* pA, const char* pB,
                                           uint32_t su, size_t kb, int tid)
{
    load_tile_cp(pA + kb, su,          tid);
    load_tile_cp(pB + kb, su + TILE_B, tid);
    CP_COMMIT();
}

template <int MODE>
__global__ __launch_bounds__(128, 2)
void gemm_mma_fp16(const __half* __restrict__ A, const __half* __restrict__ B,
                   const float* __restrict__ bias, float* __restrict__ C,
                   int ldC, const float* __restrict__ aux)
{
    extern __shared__ __align__(1024) char smem[];
    const int tid  = threadIdx.x;
    const int wid  = tid >> 5;
    const int lane = tid & 31;
    const int wm   = wid >> 1;          // 0..1
    const int wn   = wid & 1;           // 0..1
    const int m0 = blockIdx.y * 128;
    const int n0 = blockIdx.x * 128;

    if (MODE == 3) {
        // reset ticket for the subsequent MODE-1 launch (runs before it in stream order)
        if (blockIdx.z == 0 && blockIdx.x == 0 && tid == 0) g_ticket[blockIdx.y] = 0;
    }

    // K-range for this CTA
    const int cbeg = (MODE == 3) ? (int)blockIdx.z * (N_CHUNKS / KSPLIT) : 0;
    const int cend = (MODE == 3) ? cbeg + (N_CHUNKS / KSPLIT) : N_CHUNKS;

    const uint32_t sb = smem_u32(smem);

    const char* pA = (const char*)(A + (size_t)m0 * E_DIM);
    const char* pB = (const char*)(B + (size_t)n0 * E_DIM);

    float acc[4][8][4];
#pragma unroll
    for (int t = 0; t < 4; ++t)
#pragma unroll
        for (int j = 0; j < 8; ++j)
#pragma unroll
            for (int q = 0; q < 4; ++q) acc[t][j][q] = 0.f;

    const int rowA0 = wm * 64 + (lane & 15);                       // t adds 16
    const int rowB0 = wn * 64 + ((lane >> 4) << 3) + (lane & 7);   // pair p adds 16
    const int segA  = (lane >> 4);
    const int segB  = ((lane >> 3) & 1);

    load_stage(pA, pB, sb + (cbeg % N_STAGES) * STAGE_B,       (size_t)cbeg * (KC * 2),       tid);
    load_stage(pA, pB, sb + ((cbeg + 1) % N_STAGES) * STAGE_B, (size_t)(cbeg + 1) * (KC * 2), tid);

    // fragment double buffers
    uint32_t ah[2][4][4];
    uint32_t bh[2][8][2];

    for (int c = cbeg; c < cend; ++c) {
        if (c == cend - 1) { CP_WAIT(0); } else { CP_WAIT(1); }
        __syncthreads();
        if (c + 2 < cend) {
            uint32_t su = sb + ((c + 2) % N_STAGES) * STAGE_B;
            load_stage(pA, pB, su, (size_t)(c + 2) * (KC * 2), tid);
        }

        const uint32_t su = sb + (c % N_STAGES) * STAGE_B;

        // load k-step 0 fragments into buffer 0
#pragma unroll
        for (int t = 0; t < 4; ++t) {
            int row = rowA0 + t * 16;
            uint32_t off = (uint32_t)(row * 128 + ((segA ^ (row & 7)) << 4));
            ldsm4(ah[0][t][0], ah[0][t][1], ah[0][t][2], ah[0][t][3], su + off);
        }
#pragma unroll
        for (int p = 0; p < 4; ++p) {
            int row = rowB0 + p * 16;
            uint32_t off = (uint32_t)(row * 128 + ((segB ^ (row & 7)) << 4));
            ldsm4(bh[0][2 * p][0], bh[0][2 * p][1], bh[0][2 * p + 1][0], bh[0][2 * p + 1][1],
                  su + TILE_B + off);
        }

#pragma unroll
        for (int ks = 0; ks < 4; ++ks) {
            const int cur = ks & 1;
            const int nxt = cur ^ 1;
            if (ks < 3) {
#pragma unroll
                for (int t = 0; t < 4; ++t) {
                    int row = rowA0 + t * 16;
                    uint32_t off = (uint32_t)(row * 128 + ((((ks + 1) * 2 + segA) ^ (row & 7)) << 4));
                    ldsm4(ah[nxt][t][0], ah[nxt][t][1], ah[nxt][t][2], ah[nxt][t][3], su + off);
                }
#pragma unroll
                for (int p = 0; p < 4; ++p) {
                    int row = rowB0 + p * 16;
                    uint32_t off = (uint32_t)(row * 128 + ((((ks + 1) * 2 + segB) ^ (row & 7)) << 4));
                    ldsm4(bh[nxt][2 * p][0], bh[nxt][2 * p][1],
                          bh[nxt][2 * p + 1][0], bh[nxt][2 * p + 1][1],
                          su + TILE_B + off);
                }
            }
#pragma unroll
            for (int t = 0; t < 4; ++t)
#pragma unroll
                for (int j = 0; j < 8; ++j) mma16816(acc[t][j], ah[cur][t], bh[cur][j]);
        }
    }

    // local coordinates of this thread's outputs within the 128x128 tile
    const int lr0 = wm * 64 + (lane >> 2);          // + t*16, +8 for second subrow
    const int lc0 = wn * 64 + (lane & 3) * 2;       // + j*8, +1 for q-pair

    if (MODE == 1) {
        // ---- fused align epilogue ----
        float* salign = (float*)smem;                 // 128*32 floats = 16 KB
        float* kcs    = (float*)(smem + 16384);       // 128*4 floats  =  2 KB
        __syncthreads();                              // mainloop smem reads done
        for (int i = tid; i < 128 * 32; i += 128) salign[i] = 0.f;
        {
            const int d0 = n0 >> 5;
            const size_t KCP = (size_t)S_DIM * D_DIM;
            for (int i = tid; i < 128 * 4; i += 128) {
                size_t idx = (size_t)(m0 + (i >> 2)) * D_DIM + d0 + (i & 3);
                kcs[i] = g_Kc4[idx] + g_Kc4[idx + KCP] + g_Kc4[idx + 2 * KCP]
                       + g_Kc4[idx + 3 * KCP] + g_bkc[d0 + (i & 3)];
            }
        }
        __syncthreads();
#pragma unroll
        for (int t = 0; t < 4; ++t) {
#pragma unroll
            for (int sub = 0; sub < 2; ++sub) {
                int lr = lr0 + t * 16 + sub * 8;
                const float* kr = kcs + lr * 4;
#pragma unroll
                for (int jj = 0; jj < 4; ++jj) {
                    int lcA = lc0 + jj * 8;           // d = lcA>>5, h = lcA&31
                    int lcB = lcA + 32;
                    float dA = kr[lcA >> 5], dB = kr[lcB >> 5];
                    float bA = bias[n0 + lcA], bA1 = bias[n0 + lcA + 1];
                    float bB = bias[n0 + lcB], bB1 = bias[n0 + lcB + 1];
                    float p0 = dA * (acc[t][jj][2 * sub] + bA)
                             + dB * (acc[t][jj + 4][2 * sub] + bB);
                    float p1 = dA * (acc[t][jj][2 * sub + 1] + bA1)
                             + dB * (acc[t][jj + 4][2 * sub + 1] + bB1);
                    int h = lcA & 31;
                    atomicAdd(&salign[lr * 32 + h],     p0);
                    atomicAdd(&salign[lr * 32 + h + 1], p1);
                }
            }
        }
        __syncthreads();
        {
            float* dst = C + ((size_t)(m0 + tid) * NTILES + blockIdx.x) * H_DIM;
            const float* src = salign + tid * 32;
#pragma unroll
            for (int i = 0; i < 8; ++i)
                *(float4*)(dst + i * 4) = *(const float4*)(src + i * 4);
        }

        // ---- threadfence-reduction: last arriving CTA for this m-tile does softmax ----
        __threadfence();
        __shared__ int s_last;
        if (tid == 0) {
            int old = atomicAdd(&g_ticket[blockIdx.y], 1);
            s_last = (old == NTILES - 1);
        }
        __syncthreads();
        if (s_last) {
            const int* mk = (const int*)aux;
            // 4 warps, each handles rows wid, wid+4, ... (lane = h)
            for (int r = wid; r < 128; r += 4) {
                const int s = m0 + r;
                const float* p = C + (size_t)s * (NTILES * H_DIM);
                float a = 0.f;
#pragma unroll 8
                for (int t = 0; t < NTILES; ++t)
                    a += p[t * H_DIM + lane];
                a *= (1.0f / 64.0f);                       // SCALE = sqrt(4096)
                if (mk[(size_t)s * H_DIM + lane] == 0) a = 1e-20f;
                float mx = a;
#pragma unroll
                for (int o = 16; o > 0; o >>= 1) mx = fmaxf(mx, __shfl_xor_sync(0xffffffffu, mx, o));
                float e = __expf(a - mx);
                float sum = e;
#pragma unroll
                for (int o = 16; o > 0; o >>= 1) sum += __shfl_xor_sync(0xffffffffu, sum, o);
                g_Wt[(size_t)s * H_DIM + lane] = e / sum;
            }
        }
        return;
    }

    if (MODE == 3) {
        // ---- split-K partial store: no bias ----
        float* Cp = C + (size_t)blockIdx.z * ((size_t)S_DIM * D_DIM);
#pragma unroll
        for (int t = 0; t < 4; ++t) {
            int row0 = m0 + lr0 + t * 16;
#pragma unroll
            for (int j = 0; j < 8; ++j) {
                int col = n0 + lc0 + j * 8;
                *(float2*)(Cp + (size_t)row0 * ldC + col)
                    = make_float2(acc[t][j][0], acc[t][j][1]);
                *(float2*)(Cp + (size_t)(row0 + 8) * ldC + col)
                    = make_float2(acc[t][j][2], acc[t][j][3]);
            }
        }
        return;
    }

    // ---- MODE 2 epilogue ----
    const int rbase = m0 + lr0;
    const int cbase = n0 + lc0;
#pragma unroll
    for (int t = 0; t < 4; ++t) {
        int row0 = rbase + t * 16;
#pragma unroll
        for (int j = 0; j < 8; ++j) {
            int col = cbase + j * 8;
            float b0 = bias[col], b1 = bias[col + 1];
            float2 v0 = make_float2(acc[t][j][0] + b0, acc[t][j][1] + b1);
            float2 v1 = make_float2(acc[t][j][2] + b0, acc[t][j][3] + b1);
            {
                int h = col & 31;
                const float* w0 = aux + (size_t)row0 * H_DIM;
                const float* w1 = aux + (size_t)(row0 + 8) * H_DIM;
                v0.x *= w0[h]; v0.y *= w0[h + 1];
                v1.x *= w1[h]; v1.y *= w1[h + 1];
            }
            *(float2*)(C + (size_t)row0 * ldC + col)       = v0;
            *(float2*)(C + (size_t)(row0 + 8) * ldC + col) = v1;
        }
    }
}

// ---------------------------------------------------------------------------
// Launch — softmax fused into Q-GEMM tail; weight conversions off-path.
// ---------------------------------------------------------------------------
extern "C" void kernel_launch(void* const* d_in, const int* in_sizes, int n_in,
                              void* d_out, int out_size)
{
    (void)in_sizes; (void)n_in; (void)out_size;

    const float* x    = (const float*)d_in[0];
    const float* Wq   = (const float*)d_in[1];
    const float* bq   = (const float*)d_in[2];
    const float* Wk   = (const float*)d_in[3];
    const float* bk   = (const float*)d_in[4];
    const float* Wv   = (const float*)d_in[5];
    const float* bv   = (const float*)d_in[6];
    const int*   mask = (const int*)d_in[7];
    float* out = (float*)d_out;

    __half *xh, *wq, *wv, *wk;
    float *bkc, *Kc4p, *palp, *Wtp;
    cudaGetSymbolAddress((void**)&xh, g_x);
    cudaGetSymbolAddress((void**)&wq, g_wq);
    cudaGetSymbolAddress((void**)&wv, g_wv);
    cudaGetSymbolAddress((void**)&wk, g_wk);
    cudaGetSymbolAddress((void**)&bkc, g_bkc);
    cudaGetSymbolAddress((void**)&Kc4p, g_Kc4);
    cudaGetSymbolAddress((void**)&palp, g_pal);
    cudaGetSymbolAddress((void**)&Wtp, g_Wt);

    cudaFuncSetAttribute(gemm_mma_fp16<1>, cudaFuncAttributeMaxDynamicSharedMemorySize, SMEM_TOTAL);
    cudaFuncSetAttribute(gemm_mma_fp16<2>, cudaFuncAttributeMaxDynamicSharedMemorySize, SMEM_TOTAL);
    cudaFuncSetAttribute(gemm_mma_fp16<3>, cudaFuncAttributeMaxDynamicSharedMemorySize, SMEM_TOTAL);

    static cudaStream_t s2 = nullptr, s3 = nullptr, s4 = nullptr;
    static cudaEvent_t evRoot = nullptr, evWq = nullptr, evWv = nullptr, evWk = nullptr;
    if (!s2) {
        cudaStreamCreateWithFlags(&s2, cudaStreamNonBlocking);
        cudaStreamCreateWithFlags(&s3, cudaStreamNonBlocking);
        cudaStreamCreateWithFlags(&s4, cudaStreamNonBlocking);
        cudaEventCreateWithFlags(&evRoot, cudaEventDisableTiming);
        cudaEventCreateWithFlags(&evWq, cudaEventDisableTiming);
        cudaEventCreateWithFlags(&evWv, cudaEventDisableTiming);
        cudaEventCreateWithFlags(&evWk, cudaEventDisableTiming);
    }

    // fork side streams from the main (capture) stream
    cudaEventRecord(evRoot, 0);
    cudaStreamWaitEvent(s2, evRoot, 0);
    cudaStreamWaitEvent(s3, evRoot, 0);
    cudaStreamWaitEvent(s4, evRoot, 0);

    int n4x = (S_DIM * E_DIM) / 4;
    int n4w = (E_DIM * E_DIM) / 4;

    // critical path: x conversion on the main stream
    cvt_kernel<<<n4x / 256, 256>>>((const float4*)x, (__half2*)xh, n4x);
    // off-path: weight conversions on side streams
    cvt_kernel<<<n4w / 256, 256, 0, s2>>>((const float4*)Wq, (__half2*)wq, n4w);
    cudaEventRecord(evWq, s2);
    cvt_kernel<<<n4w / 256, 256, 0, s3>>>((const float4*)Wv, (__half2*)wv, n4w);
    cudaEventRecord(evWv, s3);
    gather_wk_kernel<<<(D_DIM * E_DIM / 4) / 256, 256, 0, s4>>>(Wk, bk, wk, bkc);
    cudaEventRecord(evWk, s4);

    // Kc split-K partials (needs x + Wk); also zeroes the softmax tickets
    cudaStreamWaitEvent(0, evWk, 0);
    gemm_mma_fp16<3><<<dim3(1, S_DIM / 128, KSPLIT), 128, SMEM_TOTAL>>>(xh, wk, bkc, Kc4p, D_DIM, nullptr);
    // Q GEMM with fused align + tail softmax (aux = mask)
    cudaStreamWaitEvent(0, evWq, 0);
    gemm_mma_fp16<1><<<dim3(E_DIM / 128, S_DIM / 128), 128, SMEM_TOTAL>>>(xh, wq, bq, palp, 0, (const float*)mask);
    // V GEMM (needs Wv + Wt, ordered on the main stream after Q)
    cudaStreamWaitEvent(0, evWv, 0);
    gemm_mma_fp16<2><<<dim3(E_DIM / 128, S_DIM / 128), 128, SMEM_TOTAL>>>(xh, wv, bv, out, E_DIM, Wtp);
}

// round 15
// speedup vs baseline: 1.0318x; 1.0318x over previous
#include <cuda_runtime.h>
#include <cuda_fp16.h>
#include <cstdint>
#include <cstddef>

#define S_DIM 8192
#define E_DIM 4096
#define H_DIM 32
#define D_DIM 128
#define NTILES 32                          // E_DIM / 128 n-tiles in Q GEMM
#define KSPLIT 4

// ---------------------------------------------------------------------------
// Scratch (static __device__; no allocation allowed)
// ---------------------------------------------------------------------------
__device__ __half g_x [(size_t)S_DIM * E_DIM];
__device__ __half g_wq[(size_t)E_DIM * E_DIM];
__device__ __half g_wv[(size_t)E_DIM * E_DIM];
__device__ __half g_wk[(size_t)D_DIM * E_DIM];
__device__ float  g_bkc[D_DIM];
__device__ float  g_Kc4[(size_t)KSPLIT * S_DIM * D_DIM];   // split-K partials of Kc
__device__ float  g_pal[(size_t)S_DIM * NTILES * H_DIM];   // partial align, [s][ntile][h]
__device__ float  g_Wt [(size_t)S_DIM * H_DIM];

// ---------------------------------------------------------------------------
// PTX helpers (sm_80-era: legal under plain sm_103 target)
// ---------------------------------------------------------------------------
__device__ __forceinline__ uint32_t smem_u32(const void* p) {
    uint32_t a;
    asm("{ .reg .u64 t; cvta.to.shared.u64 t, %1; cvt.u32.u64 %0, t; }" : "=r"(a) : "l"(p));
    return a;
}
__device__ __forceinline__ void cp16(uint32_t s, const void* g) {
    asm volatile("cp.async.cg.shared.global [%0], [%1], 16;" :: "r"(s), "l"(g));
}
#define CP_COMMIT() asm volatile("cp.async.commit_group;" ::: "memory")
#define CP_WAIT(n)  asm volatile("cp.async.wait_group %0;" :: "n"(n) : "memory")

__device__ __forceinline__ void ldsm4(uint32_t& r0, uint32_t& r1, uint32_t& r2, uint32_t& r3,
                                      uint32_t a) {
    asm volatile("ldmatrix.sync.aligned.m8n8.x4.shared.b16 {%0,%1,%2,%3}, [%4];"
                 : "=r"(r0), "=r"(r1), "=r"(r2), "=r"(r3) : "r"(a));
}
__device__ __forceinline__ void mma16816(float* c, const uint32_t* a, const uint32_t* b) {
    asm volatile("mma.sync.aligned.m16n8k16.row.col.f32.f16.f16.f32 "
                 "{%0,%1,%2,%3}, {%4,%5,%6,%7}, {%8,%9}, {%0,%1,%2,%3};"
                 : "+f"(c[0]), "+f"(c[1]), "+f"(c[2]), "+f"(c[3])
                 : "r"(a[0]), "r"(a[1]), "r"(a[2]), "r"(a[3]), "r"(b[0]), "r"(b[1]));
}

// ---------------------------------------------------------------------------
// fp32 -> fp16 conversion (vectorized x4)
// ---------------------------------------------------------------------------
__global__ void cvt_kernel(const float4* __restrict__ in, __half2* __restrict__ out, int n4)
{
    int i = blockIdx.x * blockDim.x + threadIdx.x;
    if (i >= n4) return;
    float4 v = in[i];
    out[2 * i]     = __halves2half2(__float2half_rn(v.x), __float2half_rn(v.y));
    out[2 * i + 1] = __halves2half2(__float2half_rn(v.z), __float2half_rn(v.w));
}

// Gather every 32nd row of Wk -> dense fp16 [128,4096], and bk -> bkc
__global__ void gather_wk_kernel(const float* __restrict__ Wk, const float* __restrict__ bk,
                                 __half* __restrict__ o, float* __restrict__ bkc)
{
    int i = blockIdx.x * blockDim.x + threadIdx.x;   // over 131072 float4s
    int r = i >> 10;
    int c4 = i & 1023;
    float4 v = *(const float4*)(Wk + ((size_t)r * H_DIM) * E_DIM + c4 * 4);
    __half2* o2 = (__half2*)(o + (size_t)r * E_DIM + c4 * 4);
    o2[0] = __halves2half2(__float2half_rn(v.x), __float2half_rn(v.y));
    o2[1] = __halves2half2(__float2half_rn(v.z), __float2half_rn(v.w));
    if (i < D_DIM) bkc[i] = bk[i * H_DIM];
}

// ---------------------------------------------------------------------------
// fp16 mma.sync GEMM:  acc = A[M,K] @ B[N,K]^T ; epilogue by MODE:
//   MODE 1: align partials from (acc+bias)*Kc    (Q GEMM -> g_pal, no C)
//   MODE 2: C = (acc + bias) * wt[m*32+(n&31)]   (V GEMM -> out)
//   MODE 3: split-K Kc partial: C[part] = acc    (Kc GEMM -> g_Kc4, no bias);
//           reads fp32 x directly (aux), converting in-kernel (A unused),
//           so it does NOT depend on the cvt_x kernel.
// CTA 128x128, 4 warps 2x2 (warp tile 64x64), KC=64, 3-stage cp.async,
// 2 CTAs/SM, register double-buffered fragments.
// ---------------------------------------------------------------------------
#define KC 64
#define TILE_B 16384                      // 128 rows x 128 bytes
#define STAGE_B (2 * TILE_B)              // A, B
#define N_STAGES 3
#define SMEM_TOTAL (N_STAGES * STAGE_B)   // 96 KB
#define N_CHUNKS (E_DIM / KC)             // 64

__device__ __forceinline__ void load_tile_cp(const char* __restrict__ g, uint32_t sdst, int tid)
{
#pragma unroll
    for (int j = 0; j < 8; ++j) {
        int i = tid + (j << 7);
        int r = i >> 3, seg = i & 7;
        uint32_t off = (uint32_t)((r << 7) + (((seg ^ (r & 7))) << 4));
        cp16(sdst + off, g + (size_t)r * (E_DIM * 2) + (seg << 4));
    }
}

__device__ __forceinline__ void load_stage(const char* pA, const char* pB,
                                           uint32_t su, size_t kb, int tid)
{
    load_tile_cp(pA + kb, su,          tid);
    load_tile_cp(pB + kb, su + TILE_B, tid);
    CP_COMMIT();
}

// MODE-3 A fill: fp32 x chunk -> fp16 swizzled smem (no global side output)
__device__ __forceinline__ void fill_a_cvt(const float* __restrict__ x32, int m0, int c,
                                           char* __restrict__ sA, int tid)
{
#pragma unroll
    for (int j = 0; j < 16; ++j) {
        int i = tid + (j << 7);          // 0..2047
        int r = i >> 4;                  // row 0..127
        int s4 = i & 15;                 // float4 index within 64-float chunk row
        const float4 v = *(const float4*)(x32 + (size_t)(m0 + r) * E_DIM + c * KC + s4 * 4);
        __half2 h0 = __halves2half2(__float2half_rn(v.x), __float2half_rn(v.y));
        __half2 h1 = __halves2half2(__float2half_rn(v.z), __float2half_rn(v.w));
        uint32_t off = (uint32_t)((r << 7) + ((((s4 >> 1) ^ (r & 7))) << 4) + ((s4 & 1) << 3));
        *(__half2*)(sA + off)     = h0;
        *(__half2*)(sA + off + 4) = h1;
    }
}

template <int MODE>
__global__ __launch_bounds__(128, 2)
void gemm_mma_fp16(const __half* __restrict__ A, const __half* __restrict__ B,
                   const float* __restrict__ bias, float* __restrict__ C,
                   int ldC, const float* __restrict__ aux)
{
    extern __shared__ __align__(1024) char smem[];
    const int tid  = threadIdx.x;
    const int wid  = tid >> 5;
    const int lane = tid & 31;
    const int wm   = wid >> 1;          // 0..1
    const int wn   = wid & 1;           // 0..1
    const int m0 = blockIdx.y * 128;
    const int n0 = blockIdx.x * 128;

    // K-range for this CTA
    const int cbeg = (MODE == 3) ? (int)blockIdx.z * (N_CHUNKS / KSPLIT) : 0;
    const int cend = (MODE == 3) ? cbeg + (N_CHUNKS / KSPLIT) : N_CHUNKS;

    const uint32_t sb = smem_u32(smem);

    const char* pA = (const char*)(A + (size_t)m0 * E_DIM);
    const char* pB = (const char*)(B + (size_t)n0 * E_DIM);

    float acc[4][8][4];
#pragma unroll
    for (int t = 0; t < 4; ++t)
#pragma unroll
        for (int j = 0; j < 8; ++j)
#pragma unroll
            for (int q = 0; q < 4; ++q) acc[t][j][q] = 0.f;

    const int rowA0 = wm * 64 + (lane & 15);                       // t adds 16
    const int rowB0 = wn * 64 + ((lane >> 4) << 3) + (lane & 7);   // pair p adds 16
    const int segA  = (lane >> 4);
    const int segB  = ((lane >> 3) & 1);

    if (MODE == 3) {
        // B-only cp.async prologue (A filled synchronously per chunk)
        load_tile_cp(pB + (size_t)cbeg * (KC * 2),
                     sb + (cbeg % N_STAGES) * STAGE_B + TILE_B, tid);
        CP_COMMIT();
        load_tile_cp(pB + (size_t)(cbeg + 1) * (KC * 2),
                     sb + ((cbeg + 1) % N_STAGES) * STAGE_B + TILE_B, tid);
        CP_COMMIT();
    } else {
        load_stage(pA, pB, sb + (cbeg % N_STAGES) * STAGE_B,       (size_t)cbeg * (KC * 2),       tid);
        load_stage(pA, pB, sb + ((cbeg + 1) % N_STAGES) * STAGE_B, (size_t)(cbeg + 1) * (KC * 2), tid);
    }

    // fragment double buffers
    uint32_t ah[2][4][4];
    uint32_t bh[2][8][2];

    for (int c = cbeg; c < cend; ++c) {
        const uint32_t su = sb + (c % N_STAGES) * STAGE_B;

        if (MODE == 3)
            fill_a_cvt(aux, m0, c, smem + (c % N_STAGES) * STAGE_B, tid);

        if (c == cend - 1) { CP_WAIT(0); } else { CP_WAIT(1); }
        __syncthreads();
        if (c + 2 < cend) {
            if (MODE == 3) {
                load_tile_cp(pB + (size_t)(c + 2) * (KC * 2),
                             sb + ((c + 2) % N_STAGES) * STAGE_B + TILE_B, tid);
                CP_COMMIT();
            } else {
                uint32_t sun = sb + ((c + 2) % N_STAGES) * STAGE_B;
                load_stage(pA, pB, sun, (size_t)(c + 2) * (KC * 2), tid);
            }
        }

        // load k-step 0 fragments into buffer 0
#pragma unroll
        for (int t = 0; t < 4; ++t) {
            int row = rowA0 + t * 16;
            uint32_t off = (uint32_t)(row * 128 + ((segA ^ (row & 7)) << 4));
            ldsm4(ah[0][t][0], ah[0][t][1], ah[0][t][2], ah[0][t][3], su + off);
        }
#pragma unroll
        for (int p = 0; p < 4; ++p) {
            int row = rowB0 + p * 16;
            uint32_t off = (uint32_t)(row * 128 + ((segB ^ (row & 7)) << 4));
            ldsm4(bh[0][2 * p][0], bh[0][2 * p][1], bh[0][2 * p + 1][0], bh[0][2 * p + 1][1],
                  su + TILE_B + off);
        }

#pragma unroll
        for (int ks = 0; ks < 4; ++ks) {
            const int cur = ks & 1;
            const int nxt = cur ^ 1;
            if (ks < 3) {
#pragma unroll
                for (int t = 0; t < 4; ++t) {
                    int row = rowA0 + t * 16;
                    uint32_t off = (uint32_t)(row * 128 + ((((ks + 1) * 2 + segA) ^ (row & 7)) << 4));
                    ldsm4(ah[nxt][t][0], ah[nxt][t][1], ah[nxt][t][2], ah[nxt][t][3], su + off);
                }
#pragma unroll
                for (int p = 0; p < 4; ++p) {
                    int row = rowB0 + p * 16;
                    uint32_t off = (uint32_t)(row * 128 + ((((ks + 1) * 2 + segB) ^ (row & 7)) << 4));
                    ldsm4(bh[nxt][2 * p][0], bh[nxt][2 * p][1],
                          bh[nxt][2 * p + 1][0], bh[nxt][2 * p + 1][1],
                          su + TILE_B + off);
                }
            }
#pragma unroll
            for (int t = 0; t < 4; ++t)
#pragma unroll
                for (int j = 0; j < 8; ++j) mma16816(acc[t][j], ah[cur][t], bh[cur][j]);
        }
    }

    // local coordinates of this thread's outputs within the 128x128 tile
    const int lr0 = wm * 64 + (lane >> 2);          // + t*16, +8 for second subrow
    const int lc0 = wn * 64 + (lane & 3) * 2;       // + j*8, +1 for q-pair

    if (MODE == 1) {
        // ---- fused align epilogue: no C write ----
        float* salign = (float*)smem;                 // 128*32 floats = 16 KB
        float* kcs    = (float*)(smem + 16384);       // 128*4 floats  =  2 KB
        __syncthreads();                              // mainloop smem reads done
        for (int i = tid; i < 128 * 32; i += 128) salign[i] = 0.f;
        {
            const int d0 = n0 >> 5;
            const size_t KCP = (size_t)S_DIM * D_DIM;
            for (int i = tid; i < 128 * 4; i += 128) {
                size_t idx = (size_t)(m0 + (i >> 2)) * D_DIM + d0 + (i & 3);
                kcs[i] = g_Kc4[idx] + g_Kc4[idx + KCP] + g_Kc4[idx + 2 * KCP]
                       + g_Kc4[idx + 3 * KCP] + g_bkc[d0 + (i & 3)];
            }
        }
        __syncthreads();
#pragma unroll
        for (int t = 0; t < 4; ++t) {
#pragma unroll
            for (int sub = 0; sub < 2; ++sub) {
                int lr = lr0 + t * 16 + sub * 8;
                const float* kr = kcs + lr * 4;
#pragma unroll
                for (int jj = 0; jj < 4; ++jj) {
                    int lcA = lc0 + jj * 8;           // d = lcA>>5, h = lcA&31
                    int lcB = lcA + 32;
                    float dA = kr[lcA >> 5], dB = kr[lcB >> 5];
                    float bA = bias[n0 + lcA], bA1 = bias[n0 + lcA + 1];
                    float bB = bias[n0 + lcB], bB1 = bias[n0 + lcB + 1];
                    float p0 = dA * (acc[t][jj][2 * sub] + bA)
                             + dB * (acc[t][jj + 4][2 * sub] + bB);
                    float p1 = dA * (acc[t][jj][2 * sub + 1] + bA1)
                             + dB * (acc[t][jj + 4][2 * sub + 1] + bB1);
                    int h = lcA & 31;
                    atomicAdd(&salign[lr * 32 + h],     p0);
                    atomicAdd(&salign[lr * 32 + h + 1], p1);
                }
            }
        }
        __syncthreads();
        {
            float* dst = C + ((size_t)(m0 + tid) * NTILES + blockIdx.x) * H_DIM;
            const float* src = salign + tid * 32;
#pragma unroll
            for (int i = 0; i < 8; ++i)
                *(float4*)(dst + i * 4) = *(const float4*)(src + i * 4);
        }
        return;
    }

    if (MODE == 3) {
        // ---- split-K partial store: no bias ----
        float* Cp = C + (size_t)blockIdx.z * ((size_t)S_DIM * D_DIM);
#pragma unroll
        for (int t = 0; t < 4; ++t) {
            int row0 = m0 + lr0 + t * 16;
#pragma unroll
            for (int j = 0; j < 8; ++j) {
                int col = n0 + lc0 + j * 8;
                *(float2*)(Cp + (size_t)row0 * ldC + col)
                    = make_float2(acc[t][j][0], acc[t][j][1]);
                *(float2*)(Cp + (size_t)(row0 + 8) * ldC + col)
                    = make_float2(acc[t][j][2], acc[t][j][3]);
            }
        }
        return;
    }

    // ---- MODE 2 epilogue ----
    const int rbase = m0 + lr0;
    const int cbase = n0 + lc0;
#pragma unroll
    for (int t = 0; t < 4; ++t) {
        int row0 = rbase + t * 16;
#pragma unroll
        for (int j = 0; j < 8; ++j) {
            int col = cbase + j * 8;
            float b0 = bias[col], b1 = bias[col + 1];
            float2 v0 = make_float2(acc[t][j][0] + b0, acc[t][j][1] + b1);
            float2 v1 = make_float2(acc[t][j][2] + b0, acc[t][j][3] + b1);
            {
                int h = col & 31;
                const float* w0 = aux + (size_t)row0 * H_DIM;
                const float* w1 = aux + (size_t)(row0 + 8) * H_DIM;
                v0.x *= w0[h]; v0.y *= w0[h + 1];
                v1.x *= w1[h]; v1.y *= w1[h + 1];
            }
            *(float2*)(C + (size_t)row0 * ldC + col)       = v0;
            *(float2*)(C + (size_t)(row0 + 8) * ldC + col) = v1;
        }
    }
}

// ---------------------------------------------------------------------------
// reduce partials + mask + softmax -> Wt.  One warp per row s.
// ---------------------------------------------------------------------------
__global__ void softmax_kernel(const float* __restrict__ pal,
                               const int* __restrict__ mask,
                               float* __restrict__ Wt)
{
    const int warp = threadIdx.x >> 5;
    const int h    = threadIdx.x & 31;
    const int s    = blockIdx.x * (blockDim.x >> 5) + warp;

    const float* p = pal + (size_t)s * NTILES * H_DIM;
    float acc = 0.f;
#pragma unroll 8
    for (int t = 0; t < NTILES; ++t)
        acc += p[t * H_DIM + h];

    acc *= (1.0f / 64.0f);                          // SCALE = sqrt(4096)
    if (mask[(size_t)s * H_DIM + h] == 0) acc = 1e-20f;

    float mx = acc;
#pragma unroll
    for (int o = 16; o > 0; o >>= 1) mx = fmaxf(mx, __shfl_xor_sync(0xffffffffu, mx, o));
    float e = __expf(acc - mx);
    float sum = e;
#pragma unroll
    for (int o = 16; o > 0; o >>= 1) sum += __shfl_xor_sync(0xffffffffu, sum, o);

    Wt[(size_t)s * H_DIM + h] = e / sum;
}

// ---------------------------------------------------------------------------
// Launch — Kc (fp32-A variant) runs on a side stream CONCURRENT with cvt_x;
// weight conversions off-path as in R12.
// ---------------------------------------------------------------------------
extern "C" void kernel_launch(void* const* d_in, const int* in_sizes, int n_in,
                              void* d_out, int out_size)
{
    (void)in_sizes; (void)n_in; (void)out_size;

    const float* x    = (const float*)d_in[0];
    const float* Wq   = (const float*)d_in[1];
    const float* bq   = (const float*)d_in[2];
    const float* Wk   = (const float*)d_in[3];
    const float* bk   = (const float*)d_in[4];
    const float* Wv   = (const float*)d_in[5];
    const float* bv   = (const float*)d_in[6];
    const int*   mask = (const int*)d_in[7];
    float* out = (float*)d_out;

    __half *xh, *wq, *wv, *wk;
    float *bkc, *Kc4p, *palp, *Wtp;
    cudaGetSymbolAddress((void**)&xh, g_x);
    cudaGetSymbolAddress((void**)&wq, g_wq);
    cudaGetSymbolAddress((void**)&wv, g_wv);
    cudaGetSymbolAddress((void**)&wk, g_wk);
    cudaGetSymbolAddress((void**)&bkc, g_bkc);
    cudaGetSymbolAddress((void**)&Kc4p, g_Kc4);
    cudaGetSymbolAddress((void**)&palp, g_pal);
    cudaGetSymbolAddress((void**)&Wtp, g_Wt);

    cudaFuncSetAttribute(gemm_mma_fp16<1>, cudaFuncAttributeMaxDynamicSharedMemorySize, SMEM_TOTAL);
    cudaFuncSetAttribute(gemm_mma_fp16<2>, cudaFuncAttributeMaxDynamicSharedMemorySize, SMEM_TOTAL);
    cudaFuncSetAttribute(gemm_mma_fp16<3>, cudaFuncAttributeMaxDynamicSharedMemorySize, SMEM_TOTAL);

    static cudaStream_t s2 = nullptr, s3 = nullptr, s4 = nullptr;
    static cudaEvent_t evRoot = nullptr, evWq = nullptr, evWv = nullptr, evKc = nullptr;
    if (!s2) {
        cudaStreamCreateWithFlags(&s2, cudaStreamNonBlocking);
        cudaStreamCreateWithFlags(&s3, cudaStreamNonBlocking);
        cudaStreamCreateWithFlags(&s4, cudaStreamNonBlocking);
        cudaEventCreateWithFlags(&evRoot, cudaEventDisableTiming);
        cudaEventCreateWithFlags(&evWq, cudaEventDisableTiming);
        cudaEventCreateWithFlags(&evWv, cudaEventDisableTiming);
        cudaEventCreateWithFlags(&evKc, cudaEventDisableTiming);
    }

    // fork side streams from the main (capture) stream
    cudaEventRecord(evRoot, 0);
    cudaStreamWaitEvent(s2, evRoot, 0);
    cudaStreamWaitEvent(s3, evRoot, 0);
    cudaStreamWaitEvent(s4, evRoot, 0);

    int n4x = (S_DIM * E_DIM) / 4;
    int n4w = (E_DIM * E_DIM) / 4;

    // main stream: x conversion (needed by Q and V GEMMs)
    cvt_kernel<<<n4x / 256, 256>>>((const float4*)x, (__half2*)xh, n4x);
    // side streams: weight conversions
    cvt_kernel<<<n4w / 256, 256, 0, s2>>>((const float4*)Wq, (__half2*)wq, n4w);
    cudaEventRecord(evWq, s2);
    cvt_kernel<<<n4w / 256, 256, 0, s3>>>((const float4*)Wv, (__half2*)wv, n4w);
    cudaEventRecord(evWv, s3);
    // side stream s4: gather Wk, then Kc split-K partials reading fp32 x
    // directly (no cvt_x dependency) -> concurrent with cvt_x
    gather_wk_kernel<<<(D_DIM * E_DIM / 4) / 256, 256, 0, s4>>>(Wk, bk, wk, bkc);
    gemm_mma_fp16<3><<<dim3(1, S_DIM / 128, KSPLIT), 128, SMEM_TOTAL, s4>>>(nullptr, wk, bkc, Kc4p, D_DIM, x);
    cudaEventRecord(evKc, s4);

    // Q GEMM with fused align epilogue (needs xh + Wq + Kc partials)
    cudaStreamWaitEvent(0, evWq, 0);
    cudaStreamWaitEvent(0, evKc, 0);
    gemm_mma_fp16<1><<<dim3(E_DIM / 128, S_DIM / 128), 128, SMEM_TOTAL>>>(xh, wq, bq, palp, 0, nullptr);
    // reduce + mask + softmax
    softmax_kernel<<<S_DIM / 8, 256>>>(palp, mask, Wtp);
    // V GEMM (needs Wv + Wt)
    cudaStreamWaitEvent(0, evWv, 0);
    gemm_mma_fp16<2><<<dim3(E_DIM / 128, S_DIM / 128), 128, SMEM_TOTAL>>>(xh, wv, bv, out, E_DIM, Wtp);
}

// round 16
// speedup vs baseline: 1.0641x; 1.0313x over previous
#include <cuda_runtime.h>
#include <cuda_fp16.h>
#include <cstdint>
#include <cstddef>

#define S_DIM 8192
#define E_DIM 4096
#define H_DIM 32
#define D_DIM 128
#define NTILES 32                          // E_DIM / 128 n-tiles in Q GEMM
#define KSPLIT 4

// ---------------------------------------------------------------------------
// Scratch (static __device__; no allocation allowed)
// ---------------------------------------------------------------------------
__device__ __half g_x [(size_t)S_DIM * E_DIM];
__device__ __half g_wq[(size_t)E_DIM * E_DIM];
__device__ __half g_wv[(size_t)E_DIM * E_DIM];
__device__ __half g_wk[(size_t)D_DIM * E_DIM];
__device__ float  g_bkc[D_DIM];
__device__ float  g_Kc4[(size_t)KSPLIT * S_DIM * D_DIM];   // split-K partials of Kc
__device__ float  g_pal[(size_t)S_DIM * NTILES * H_DIM];   // partial align, [s][ntile][h]
__device__ float  g_Wt [(size_t)S_DIM * H_DIM];

// ---------------------------------------------------------------------------
// PTX helpers (sm_80-era: legal under plain sm_103 target)
// ---------------------------------------------------------------------------
__device__ __forceinline__ uint32_t smem_u32(const void* p) {
    uint32_t a;
    asm("{ .reg .u64 t; cvta.to.shared.u64 t, %1; cvt.u32.u64 %0, t; }" : "=r"(a) : "l"(p));
    return a;
}
__device__ __forceinline__ void cp16(uint32_t s, const void* g) {
    asm volatile("cp.async.cg.shared.global [%0], [%1], 16;" :: "r"(s), "l"(g));
}
#define CP_COMMIT() asm volatile("cp.async.commit_group;" ::: "memory")
#define CP_WAIT(n)  asm volatile("cp.async.wait_group %0;" :: "n"(n) : "memory")

__device__ __forceinline__ void ldsm4(uint32_t& r0, uint32_t& r1, uint32_t& r2, uint32_t& r3,
                                      uint32_t a) {
    asm volatile("ldmatrix.sync.aligned.m8n8.x4.shared.b16 {%0,%1,%2,%3}, [%4];"
                 : "=r"(r0), "=r"(r1), "=r"(r2), "=r"(r3) : "r"(a));
}
__device__ __forceinline__ void mma16816(float* c, const uint32_t* a, const uint32_t* b) {
    asm volatile("mma.sync.aligned.m16n8k16.row.col.f32.f16.f16.f32 "
                 "{%0,%1,%2,%3}, {%4,%5,%6,%7}, {%8,%9}, {%0,%1,%2,%3};"
                 : "+f"(c[0]), "+f"(c[1]), "+f"(c[2]), "+f"(c[3])
                 : "r"(a[0]), "r"(a[1]), "r"(a[2]), "r"(a[3]), "r"(b[0]), "r"(b[1]));
}
// streaming store: write-through hint, no L2 allocation pressure (never re-read)
__device__ __forceinline__ void stwt2(float* p, float2 v) {
    asm volatile("st.global.wt.v2.f32 [%0], {%1, %2};" :: "l"(p), "f"(v.x), "f"(v.y) : "memory");
}

// ---------------------------------------------------------------------------
// fp32 -> fp16 conversion (vectorized x4)
// ---------------------------------------------------------------------------
__global__ void cvt_kernel(const float4* __restrict__ in, __half2* __restrict__ out, int n4)
{
    int i = blockIdx.x * blockDim.x + threadIdx.x;
    if (i >= n4) return;
    float4 v = in[i];
    out[2 * i]     = __halves2half2(__float2half_rn(v.x), __float2half_rn(v.y));
    out[2 * i + 1] = __halves2half2(__float2half_rn(v.z), __float2half_rn(v.w));
}

// Gather every 32nd row of Wk -> dense fp16 [128,4096], and bk -> bkc
__global__ void gather_wk_kernel(const float* __restrict__ Wk, const float* __restrict__ bk,
                                 __half* __restrict__ o, float* __restrict__ bkc)
{
    int i = blockIdx.x * blockDim.x + threadIdx.x;   // over 131072 float4s
    int r = i >> 10;
    int c4 = i & 1023;
    float4 v = *(const float4*)(Wk + ((size_t)r * H_DIM) * E_DIM + c4 * 4);
    __half2* o2 = (__half2*)(o + (size_t)r * E_DIM + c4 * 4);
    o2[0] = __halves2half2(__float2half_rn(v.x), __float2half_rn(v.y));
    o2[1] = __halves2half2(__float2half_rn(v.z), __float2half_rn(v.w));
    if (i < D_DIM) bkc[i] = bk[i * H_DIM];
}

// ---------------------------------------------------------------------------
// fp16 mma.sync GEMM:  acc = A[M,K] @ B[N,K]^T ; epilogue by MODE:
//   MODE 1: align partials from (acc+bias)*Kc    (Q GEMM -> g_pal, no C)
//   MODE 2: C = (acc + bias) * wt[m*32+(n&31)]   (V GEMM -> out, streaming st)
//   MODE 3: split-K Kc partial: C[part] = acc    (Kc GEMM -> g_Kc4, no bias)
// CTA 128x128, 4 warps 2x2 (warp tile 64x64), KC=64, 3-stage cp.async,
// 2 CTAs/SM, register double-buffered fragments.
// ---------------------------------------------------------------------------
#define KC 64
#define TILE_B 16384                      // 128 rows x 128 bytes
#define STAGE_B (2 * TILE_B)              // A, B
#define N_STAGES 3
#define SMEM_TOTAL (N_STAGES * STAGE_B)   // 96 KB
#define N_CHUNKS (E_DIM / KC)             // 64

__device__ __forceinline__ void load_tile_cp(const char* __restrict__ g, uint32_t sdst, int tid)
{
#pragma unroll
    for (int j = 0; j < 8; ++j) {
        int i = tid + (j << 7);
        int r = i >> 3, seg = i & 7;
        uint32_t off = (uint32_t)((r << 7) + (((seg ^ (r & 7))) << 4));
        cp16(sdst + off, g + (size_t)r * (E_DIM * 2) + (seg << 4));
    }
}

__device__ __forceinline__ void load_stage(const char* pA, const char* pB,
                                           uint32_t su, size_t kb, int tid)
{
    load_tile_cp(pA + kb, su,          tid);
    load_tile_cp(pB + kb, su + TILE_B, tid);
    CP_COMMIT();
}

template <int MODE>
__global__ __launch_bounds__(128, 2)
void gemm_mma_fp16(const __half* __restrict__ A, const __half* __restrict__ B,
                   const float* __restrict__ bias, float* __restrict__ C,
                   int ldC, const float* __restrict__ aux)
{
    extern __shared__ __align__(1024) char smem[];
    const int tid  = threadIdx.x;
    const int wid  = tid >> 5;
    const int lane = tid & 31;
    const int wm   = wid >> 1;          // 0..1
    const int wn   = wid & 1;           // 0..1
    const int m0 = blockIdx.y * 128;
    const int n0 = blockIdx.x * 128;

    // K-range for this CTA
    const int cbeg = (MODE == 3) ? (int)blockIdx.z * (N_CHUNKS / KSPLIT) : 0;
    const int cend = (MODE == 3) ? cbeg + (N_CHUNKS / KSPLIT) : N_CHUNKS;

    const uint32_t sb = smem_u32(smem);

    const char* pA = (const char*)(A + (size_t)m0 * E_DIM);
    const char* pB = (const char*)(B + (size_t)n0 * E_DIM);

    float acc[4][8][4];
#pragma unroll
    for (int t = 0; t < 4; ++t)
#pragma unroll
        for (int j = 0; j < 8; ++j)
#pragma unroll
            for (int q = 0; q < 4; ++q) acc[t][j][q] = 0.f;

    const int rowA0 = wm * 64 + (lane & 15);                       // t adds 16
    const int rowB0 = wn * 64 + ((lane >> 4) << 3) + (lane & 7);   // pair p adds 16
    const int segA  = (lane >> 4);
    const int segB  = ((lane >> 3) & 1);

    load_stage(pA, pB, sb + (cbeg % N_STAGES) * STAGE_B,       (size_t)cbeg * (KC * 2),       tid);
    load_stage(pA, pB, sb + ((cbeg + 1) % N_STAGES) * STAGE_B, (size_t)(cbeg + 1) * (KC * 2), tid);

    // fragment double buffers
    uint32_t ah[2][4][4];
    uint32_t bh[2][8][2];

    for (int c = cbeg; c < cend; ++c) {
        if (c == cend - 1) { CP_WAIT(0); } else { CP_WAIT(1); }
        __syncthreads();
        if (c + 2 < cend) {
            uint32_t su = sb + ((c + 2) % N_STAGES) * STAGE_B;
            load_stage(pA, pB, su, (size_t)(c + 2) * (KC * 2), tid);
        }

        const uint32_t su = sb + (c % N_STAGES) * STAGE_B;

        // load k-step 0 fragments into buffer 0
#pragma unroll
        for (int t = 0; t < 4; ++t) {
            int row = rowA0 + t * 16;
            uint32_t off = (uint32_t)(row * 128 + ((segA ^ (row & 7)) << 4));
            ldsm4(ah[0][t][0], ah[0][t][1], ah[0][t][2], ah[0][t][3], su + off);
        }
#pragma unroll
        for (int p = 0; p < 4; ++p) {
            int row = rowB0 + p * 16;
            uint32_t off = (uint32_t)(row * 128 + ((segB ^ (row & 7)) << 4));
            ldsm4(bh[0][2 * p][0], bh[0][2 * p][1], bh[0][2 * p + 1][0], bh[0][2 * p + 1][1],
                  su + TILE_B + off);
        }

#pragma unroll
        for (int ks = 0; ks < 4; ++ks) {
            const int cur = ks & 1;
            const int nxt = cur ^ 1;
            if (ks < 3) {
#pragma unroll
                for (int t = 0; t < 4; ++t) {
                    int row = rowA0 + t * 16;
                    uint32_t off = (uint32_t)(row * 128 + ((((ks + 1) * 2 + segA) ^ (row & 7)) << 4));
                    ldsm4(ah[nxt][t][0], ah[nxt][t][1], ah[nxt][t][2], ah[nxt][t][3], su + off);
                }
#pragma unroll
                for (int p = 0; p < 4; ++p) {
                    int row = rowB0 + p * 16;
                    uint32_t off = (uint32_t)(row * 128 + ((((ks + 1) * 2 + segB) ^ (row & 7)) << 4));
                    ldsm4(bh[nxt][2 * p][0], bh[nxt][2 * p][1],
                          bh[nxt][2 * p + 1][0], bh[nxt][2 * p + 1][1],
                          su + TILE_B + off);
                }
            }
#pragma unroll
            for (int t = 0; t < 4; ++t)
#pragma unroll
                for (int j = 0; j < 8; ++j) mma16816(acc[t][j], ah[cur][t], bh[cur][j]);
        }
    }

    // local coordinates of this thread's outputs within the 128x128 tile
    const int lr0 = wm * 64 + (lane >> 2);          // + t*16, +8 for second subrow
    const int lc0 = wn * 64 + (lane & 3) * 2;       // + j*8, +1 for q-pair

    if (MODE == 1) {
        // ---- fused align epilogue: no C write ----
        float* salign = (float*)smem;                 // 128*32 floats = 16 KB
        float* kcs    = (float*)(smem + 16384);       // 128*4 floats  =  2 KB
        __syncthreads();                              // mainloop smem reads done
        for (int i = tid; i < 128 * 32; i += 128) salign[i] = 0.f;
        {
            const int d0 = n0 >> 5;
            const size_t KCP = (size_t)S_DIM * D_DIM;
            for (int i = tid; i < 128 * 4; i += 128) {
                size_t idx = (size_t)(m0 + (i >> 2)) * D_DIM + d0 + (i & 3);
                kcs[i] = g_Kc4[idx] + g_Kc4[idx + KCP] + g_Kc4[idx + 2 * KCP]
                       + g_Kc4[idx + 3 * KCP] + g_bkc[d0 + (i & 3)];
            }
        }
        __syncthreads();
#pragma unroll
        for (int t = 0; t < 4; ++t) {
#pragma unroll
            for (int sub = 0; sub < 2; ++sub) {
                int lr = lr0 + t * 16 + sub * 8;
                const float* kr = kcs + lr * 4;
#pragma unroll
                for (int jj = 0; jj < 4; ++jj) {
                    int lcA = lc0 + jj * 8;           // d = lcA>>5, h = lcA&31
                    int lcB = lcA + 32;
                    float dA = kr[lcA >> 5], dB = kr[lcB >> 5];
                    float bA = bias[n0 + lcA], bA1 = bias[n0 + lcA + 1];
                    float bB = bias[n0 + lcB], bB1 = bias[n0 + lcB + 1];
                    float p0 = dA * (acc[t][jj][2 * sub] + bA)
                             + dB * (acc[t][jj + 4][2 * sub] + bB);
                    float p1 = dA * (acc[t][jj][2 * sub + 1] + bA1)
                             + dB * (acc[t][jj + 4][2 * sub + 1] + bB1);
                    int h = lcA & 31;
                    atomicAdd(&salign[lr * 32 + h],     p0);
                    atomicAdd(&salign[lr * 32 + h + 1], p1);
                }
            }
        }
        __syncthreads();
        {
            float* dst = C + ((size_t)(m0 + tid) * NTILES + blockIdx.x) * H_DIM;
            const float* src = salign + tid * 32;
#pragma unroll
            for (int i = 0; i < 8; ++i)
                *(float4*)(dst + i * 4) = *(const float4*)(src + i * 4);
        }
        return;
    }

    if (MODE == 3) {
        // ---- split-K partial store: no bias ----
        float* Cp = C + (size_t)blockIdx.z * ((size_t)S_DIM * D_DIM);
#pragma unroll
        for (int t = 0; t < 4; ++t) {
            int row0 = m0 + lr0 + t * 16;
#pragma unroll
            for (int j = 0; j < 8; ++j) {
                int col = n0 + lc0 + j * 8;
                *(float2*)(Cp + (size_t)row0 * ldC + col)
                    = make_float2(acc[t][j][0], acc[t][j][1]);
                *(float2*)(Cp + (size_t)(row0 + 8) * ldC + col)
                    = make_float2(acc[t][j][2], acc[t][j][3]);
            }
        }
        return;
    }

    // ---- MODE 2 epilogue (streaming stores: out is never re-read) ----
    const int rbase = m0 + lr0;
    const int cbase = n0 + lc0;
#pragma unroll
    for (int t = 0; t < 4; ++t) {
        int row0 = rbase + t * 16;
#pragma unroll
        for (int j = 0; j < 8; ++j) {
            int col = cbase + j * 8;
            float b0 = bias[col], b1 = bias[col + 1];
            float2 v0 = make_float2(acc[t][j][0] + b0, acc[t][j][1] + b1);
            float2 v1 = make_float2(acc[t][j][2] + b0, acc[t][j][3] + b1);
            {
                int h = col & 31;
                const float* w0 = aux + (size_t)row0 * H_DIM;
                const float* w1 = aux + (size_t)(row0 + 8) * H_DIM;
                v0.x *= w0[h]; v0.y *= w0[h + 1];
                v1.x *= w1[h]; v1.y *= w1[h + 1];
            }
            stwt2(C + (size_t)row0 * ldC + col,       v0);
            stwt2(C + (size_t)(row0 + 8) * ldC + col, v1);
        }
    }
}

// ---------------------------------------------------------------------------
// reduce partials + mask + softmax -> Wt.  One warp per row s.
// ---------------------------------------------------------------------------
__global__ void softmax_kernel(const float* __restrict__ pal,
                               const int* __restrict__ mask,
                               float* __restrict__ Wt)
{
    const int warp = threadIdx.x >> 5;
    const int h    = threadIdx.x & 31;
    const int s    = blockIdx.x * (blockDim.x >> 5) + warp;

    const float* p = pal + (size_t)s * NTILES * H_DIM;
    float acc = 0.f;
#pragma unroll 8
    for (int t = 0; t < NTILES; ++t)
        acc += p[t * H_DIM + h];

    acc *= (1.0f / 64.0f);                          // SCALE = sqrt(4096)
    if (mask[(size_t)s * H_DIM + h] == 0) acc = 1e-20f;

    float mx = acc;
#pragma unroll
    for (int o = 16; o > 0; o >>= 1) mx = fmaxf(mx, __shfl_xor_sync(0xffffffffu, mx, o));
    float e = __expf(acc - mx);
    float sum = e;
#pragma unroll
    for (int o = 16; o > 0; o >>= 1) sum += __shfl_xor_sync(0xffffffffu, sum, o);

    Wt[(size_t)s * H_DIM + h] = e / sum;
}

// ---------------------------------------------------------------------------
// Launch — R12 schedule: weight conversions off-path on side streams.
// ---------------------------------------------------------------------------
extern "C" void kernel_launch(void* const* d_in, const int* in_sizes, int n_in,
                              void* d_out, int out_size)
{
    (void)in_sizes; (void)n_in; (void)out_size;

    const float* x    = (const float*)d_in[0];
    const float* Wq   = (const float*)d_in[1];
    const float* bq   = (const float*)d_in[2];
    const float* Wk   = (const float*)d_in[3];
    const float* bk   = (const float*)d_in[4];
    const float* Wv   = (const float*)d_in[5];
    const float* bv   = (const float*)d_in[6];
    const int*   mask = (const int*)d_in[7];
    float* out = (float*)d_out;

    __half *xh, *wq, *wv, *wk;
    float *bkc, *Kc4p, *palp, *Wtp;
    cudaGetSymbolAddress((void**)&xh, g_x);
    cudaGetSymbolAddress((void**)&wq, g_wq);
    cudaGetSymbolAddress((void**)&wv, g_wv);
    cudaGetSymbolAddress((void**)&wk, g_wk);
    cudaGetSymbolAddress((void**)&bkc, g_bkc);
    cudaGetSymbolAddress((void**)&Kc4p, g_Kc4);
    cudaGetSymbolAddress((void**)&palp, g_pal);
    cudaGetSymbolAddress((void**)&Wtp, g_Wt);

    cudaFuncSetAttribute(gemm_mma_fp16<1>, cudaFuncAttributeMaxDynamicSharedMemorySize, SMEM_TOTAL);
    cudaFuncSetAttribute(gemm_mma_fp16<2>, cudaFuncAttributeMaxDynamicSharedMemorySize, SMEM_TOTAL);
    cudaFuncSetAttribute(gemm_mma_fp16<3>, cudaFuncAttributeMaxDynamicSharedMemorySize, SMEM_TOTAL);

    static cudaStream_t s2 = nullptr, s3 = nullptr, s4 = nullptr;
    static cudaEvent_t evRoot = nullptr, evWq = nullptr, evWv = nullptr, evWk = nullptr;
    if (!s2) {
        cudaStreamCreateWithFlags(&s2, cudaStreamNonBlocking);
        cudaStreamCreateWithFlags(&s3, cudaStreamNonBlocking);
        cudaStreamCreateWithFlags(&s4, cudaStreamNonBlocking);
        cudaEventCreateWithFlags(&evRoot, cudaEventDisableTiming);
        cudaEventCreateWithFlags(&evWq, cudaEventDisableTiming);
        cudaEventCreateWithFlags(&evWv, cudaEventDisableTiming);
        cudaEventCreateWithFlags(&evWk, cudaEventDisableTiming);
    }

    // fork side streams from the main (capture) stream
    cudaEventRecord(evRoot, 0);
    cudaStreamWaitEvent(s2, evRoot, 0);
    cudaStreamWaitEvent(s3, evRoot, 0);
    cudaStreamWaitEvent(s4, evRoot, 0);

    int n4x = (S_DIM * E_DIM) / 4;
    int n4w = (E_DIM * E_DIM) / 4;

    // critical path: x conversion on the main stream
    cvt_kernel<<<n4x / 256, 256>>>((const float4*)x, (__half2*)xh, n4x);
    // off-path: weight conversions on side streams
    cvt_kernel<<<n4w / 256, 256, 0, s2>>>((const float4*)Wq, (__half2*)wq, n4w);
    cudaEventRecord(evWq, s2);
    cvt_kernel<<<n4w / 256, 256, 0, s3>>>((const float4*)Wv, (__half2*)wv, n4w);
    cudaEventRecord(evWv, s3);
    gather_wk_kernel<<<(D_DIM * E_DIM / 4) / 256, 256, 0, s4>>>(Wk, bk, wk, bkc);
    cudaEventRecord(evWk, s4);

    // Kc split-K partials (needs x + Wk)
    cudaStreamWaitEvent(0, evWk, 0);
    gemm_mma_fp16<3><<<dim3(1, S_DIM / 128, KSPLIT), 128, SMEM_TOTAL>>>(xh, wk, bkc, Kc4p, D_DIM, nullptr);
    // Q GEMM with fused align epilogue (needs Wq + Kc partials)
    cudaStreamWaitEvent(0, evWq, 0);
    gemm_mma_fp16<1><<<dim3(E_DIM / 128, S_DIM / 128), 128, SMEM_TOTAL>>>(xh, wq, bq, palp, 0, nullptr);
    // reduce + mask + softmax
    softmax_kernel<<<S_DIM / 8, 256>>>(palp, mask, Wtp);
    // V GEMM (needs Wv + Wt)
    cudaStreamWaitEvent(0, evWv, 0);
    gemm_mma_fp16<2><<<dim3(E_DIM / 128, S_DIM / 128), 128, SMEM_TOTAL>>>(xh, wv, bv, out, E_DIM, Wtp);
}

// round 17
// speedup vs baseline: 1.1119x; 1.0449x over previous
#include <cuda_runtime.h>
#include <cuda_fp16.h>
#include <cstdint>
#include <cstddef>

#define S_DIM 8192
#define E_DIM 4096
#define H_DIM 32
#define D_DIM 128
#define NTILES 32                          // E_DIM / 128 n-tiles in Q GEMM
#define KSPLIT 4

// ---------------------------------------------------------------------------
// Scratch (static __device__; no allocation allowed)
// ---------------------------------------------------------------------------
__device__ __half g_x [(size_t)S_DIM * E_DIM];
__device__ __half g_wq[(size_t)E_DIM * E_DIM];
__device__ __half g_wv[(size_t)E_DIM * E_DIM];
__device__ __half g_wk[(size_t)D_DIM * E_DIM];
__device__ float  g_bkc[D_DIM];
__device__ float  g_Kc4[(size_t)KSPLIT * S_DIM * D_DIM];   // split-K partials of Kc
__device__ float  g_pal[(size_t)S_DIM * NTILES * H_DIM];   // partial align, [s][ntile][h]
__device__ float  g_Wt [(size_t)S_DIM * H_DIM];

// ---------------------------------------------------------------------------
// PTX helpers (sm_80-era: legal under plain sm_103 target)
// ---------------------------------------------------------------------------
__device__ __forceinline__ uint32_t smem_u32(const void* p) {
    uint32_t a;
    asm("{ .reg .u64 t; cvta.to.shared.u64 t, %1; cvt.u32.u64 %0, t; }" : "=r"(a) : "l"(p));
    return a;
}
__device__ __forceinline__ void cp16(uint32_t s, const void* g) {
    asm volatile("cp.async.cg.shared.global [%0], [%1], 16;" :: "r"(s), "l"(g));
}
#define CP_COMMIT() asm volatile("cp.async.commit_group;" ::: "memory")
#define CP_WAIT(n)  asm volatile("cp.async.wait_group %0;" :: "n"(n) : "memory")

__device__ __forceinline__ void ldsm4(uint32_t& r0, uint32_t& r1, uint32_t& r2, uint32_t& r3,
                                      uint32_t a) {
    asm volatile("ldmatrix.sync.aligned.m8n8.x4.shared.b16 {%0,%1,%2,%3}, [%4];"
                 : "=r"(r0), "=r"(r1), "=r"(r2), "=r"(r3) : "r"(a));
}
__device__ __forceinline__ void mma16816(float* c, const uint32_t* a, const uint32_t* b) {
    asm volatile("mma.sync.aligned.m16n8k16.row.col.f32.f16.f16.f32 "
                 "{%0,%1,%2,%3}, {%4,%5,%6,%7}, {%8,%9}, {%0,%1,%2,%3};"
                 : "+f"(c[0]), "+f"(c[1]), "+f"(c[2]), "+f"(c[3])
                 : "r"(a[0]), "r"(a[1]), "r"(a[2]), "r"(a[3]), "r"(b[0]), "r"(b[1]));
}

// ---------------------------------------------------------------------------
// fp32 -> fp16 conversion (vectorized x4)
// ---------------------------------------------------------------------------
__global__ void cvt_kernel(const float4* __restrict__ in, __half2* __restrict__ out, int n4)
{
    int i = blockIdx.x * blockDim.x + threadIdx.x;
    if (i >= n4) return;
    float4 v = in[i];
    out[2 * i]     = __halves2half2(__float2half_rn(v.x), __float2half_rn(v.y));
    out[2 * i + 1] = __halves2half2(__float2half_rn(v.z), __float2half_rn(v.w));
}

// Gather every 32nd row of Wk -> dense fp16 [128,4096], and bk -> bkc
__global__ void gather_wk_kernel(const float* __restrict__ Wk, const float* __restrict__ bk,
                                 __half* __restrict__ o, float* __restrict__ bkc)
{
    int i = blockIdx.x * blockDim.x + threadIdx.x;   // over 131072 float4s
    int r = i >> 10;
    int c4 = i & 1023;
    float4 v = *(const float4*)(Wk + ((size_t)r * H_DIM) * E_DIM + c4 * 4);
    __half2* o2 = (__half2*)(o + (size_t)r * E_DIM + c4 * 4);
    o2[0] = __halves2half2(__float2half_rn(v.x), __float2half_rn(v.y));
    o2[1] = __halves2half2(__float2half_rn(v.z), __float2half_rn(v.w));
    if (i < D_DIM) bkc[i] = bk[i * H_DIM];
}

// ---------------------------------------------------------------------------
// fp16 mma.sync GEMM:  acc = A[M,K] @ B[N,K]^T ; epilogue by MODE:
//   MODE 1: align partials from (acc+bias)*Kc    (Q GEMM -> g_pal, no C)
//   MODE 2: C = (acc + bias) * wt[m*32+(n&31)]   (V GEMM -> out)
//   MODE 3: split-K Kc partial: C[part] = acc    (Kc GEMM -> g_Kc4, no bias)
// CTA 128x128, 4 warps 2x2 (warp tile 64x64), KC=64, 3-stage cp.async,
// 2 CTAs/SM, register double-buffered fragments.
// Chunk-start ordering: ks0 fragment ldmatrix issue BEFORE the next-stage
// cp.async flood, so fragment wavefronts are not queued behind ~512
// prefetch wavefronts in the per-SM L1tex FIFO.
// ---------------------------------------------------------------------------
#define KC 64
#define TILE_B 16384                      // 128 rows x 128 bytes
#define STAGE_B (2 * TILE_B)              // A, B
#define N_STAGES 3
#define SMEM_TOTAL (N_STAGES * STAGE_B)   // 96 KB
#define N_CHUNKS (E_DIM / KC)             // 64

__device__ __forceinline__ void load_tile_cp(const char* __restrict__ g, uint32_t sdst, int tid)
{
#pragma unroll
    for (int j = 0; j < 8; ++j) {
        int i = tid + (j << 7);
        int r = i >> 3, seg = i & 7;
        uint32_t off = (uint32_t)((r << 7) + (((seg ^ (r & 7))) << 4));
        cp16(sdst + off, g + (size_t)r * (E_DIM * 2) + (seg << 4));
    }
}

__device__ __forceinline__ void load_stage(const char* pA, const char* pB,
                                           uint32_t su, size_t kb, int tid)
{
    load_tile_cp(pA + kb, su,          tid);
    load_tile_cp(pB + kb, su + TILE_B, tid);
    CP_COMMIT();
}

template <int MODE>
__global__ __launch_bounds__(128, 2)
void gemm_mma_fp16(const __half* __restrict__ A, const __half* __restrict__ B,
                   const float* __restrict__ bias, float* __restrict__ C,
                   int ldC, const float* __restrict__ aux)
{
    extern __shared__ __align__(1024) char smem[];
    const int tid  = threadIdx.x;
    const int wid  = tid >> 5;
    const int lane = tid & 31;
    const int wm   = wid >> 1;          // 0..1
    const int wn   = wid & 1;           // 0..1
    const int m0 = blockIdx.y * 128;
    const int n0 = blockIdx.x * 128;

    // K-range for this CTA
    const int cbeg = (MODE == 3) ? (int)blockIdx.z * (N_CHUNKS / KSPLIT) : 0;
    const int cend = (MODE == 3) ? cbeg + (N_CHUNKS / KSPLIT) : N_CHUNKS;

    const uint32_t sb = smem_u32(smem);

    const char* pA = (const char*)(A + (size_t)m0 * E_DIM);
    const char* pB = (const char*)(B + (size_t)n0 * E_DIM);

    float acc[4][8][4];
#pragma unroll
    for (int t = 0; t < 4; ++t)
#pragma unroll
        for (int j = 0; j < 8; ++j)
#pragma unroll
            for (int q = 0; q < 4; ++q) acc[t][j][q] = 0.f;

    const int rowA0 = wm * 64 + (lane & 15);                       // t adds 16
    const int rowB0 = wn * 64 + ((lane >> 4) << 3) + (lane & 7);   // pair p adds 16
    const int segA  = (lane >> 4);
    const int segB  = ((lane >> 3) & 1);

    load_stage(pA, pB, sb + (cbeg % N_STAGES) * STAGE_B,       (size_t)cbeg * (KC * 2),       tid);
    load_stage(pA, pB, sb + ((cbeg + 1) % N_STAGES) * STAGE_B, (size_t)(cbeg + 1) * (KC * 2), tid);

    // fragment double buffers
    uint32_t ah[2][4][4];
    uint32_t bh[2][8][2];

    for (int c = cbeg; c < cend; ++c) {
        if (c == cend - 1) { CP_WAIT(0); } else { CP_WAIT(1); }
        __syncthreads();

        const uint32_t su = sb + (c % N_STAGES) * STAGE_B;

        // load k-step 0 fragments into buffer 0 FIRST (ahead of the cp flood)
#pragma unroll
        for (int t = 0; t < 4; ++t) {
            int row = rowA0 + t * 16;
            uint32_t off = (uint32_t)(row * 128 + ((segA ^ (row & 7)) << 4));
            ldsm4(ah[0][t][0], ah[0][t][1], ah[0][t][2], ah[0][t][3], su + off);
        }
#pragma unroll
        for (int p = 0; p < 4; ++p) {
            int row = rowB0 + p * 16;
            uint32_t off = (uint32_t)(row * 128 + ((segB ^ (row & 7)) << 4));
            ldsm4(bh[0][2 * p][0], bh[0][2 * p][1], bh[0][2 * p + 1][0], bh[0][2 * p + 1][1],
                  su + TILE_B + off);
        }

        // now issue the next-stage prefetch (drains under the MMA blocks)
        if (c + 2 < cend) {
            uint32_t sun = sb + ((c + 2) % N_STAGES) * STAGE_B;
            load_stage(pA, pB, sun, (size_t)(c + 2) * (KC * 2), tid);
        }

#pragma unroll
        for (int ks = 0; ks < 4; ++ks) {
            const int cur = ks & 1;
            const int nxt = cur ^ 1;
            if (ks < 3) {
#pragma unroll
                for (int t = 0; t < 4; ++t) {
                    int row = rowA0 + t * 16;
                    uint32_t off = (uint32_t)(row * 128 + ((((ks + 1) * 2 + segA) ^ (row & 7)) << 4));
                    ldsm4(ah[nxt][t][0], ah[nxt][t][1], ah[nxt][t][2], ah[nxt][t][3], su + off);
                }
#pragma unroll
                for (int p = 0; p < 4; ++p) {
                    int row = rowB0 + p * 16;
                    uint32_t off = (uint32_t)(row * 128 + ((((ks + 1) * 2 + segB) ^ (row & 7)) << 4));
                    ldsm4(bh[nxt][2 * p][0], bh[nxt][2 * p][1],
                          bh[nxt][2 * p + 1][0], bh[nxt][2 * p + 1][1],
                          su + TILE_B + off);
                }
            }
#pragma unroll
            for (int t = 0; t < 4; ++t)
#pragma unroll
                for (int j = 0; j < 8; ++j) mma16816(acc[t][j], ah[cur][t], bh[cur][j]);
        }
    }

    // local coordinates of this thread's outputs within the 128x128 tile
    const int lr0 = wm * 64 + (lane >> 2);          // + t*16, +8 for second subrow
    const int lc0 = wn * 64 + (lane & 3) * 2;       // + j*8, +1 for q-pair

    if (MODE == 1) {
        // ---- fused align epilogue: no C write ----
        float* salign = (float*)smem;                 // 128*32 floats = 16 KB
        float* kcs    = (float*)(smem + 16384);       // 128*4 floats  =  2 KB
        __syncthreads();                              // mainloop smem reads done
        for (int i = tid; i < 128 * 32; i += 128) salign[i] = 0.f;
        {
            const int d0 = n0 >> 5;
            const size_t KCP = (size_t)S_DIM * D_DIM;
            for (int i = tid; i < 128 * 4; i += 128) {
                size_t idx = (size_t)(m0 + (i >> 2)) * D_DIM + d0 + (i & 3);
                kcs[i] = g_Kc4[idx] + g_Kc4[idx + KCP] + g_Kc4[idx + 2 * KCP]
                       + g_Kc4[idx + 3 * KCP] + g_bkc[d0 + (i & 3)];
            }
        }
        __syncthreads();
#pragma unroll
        for (int t = 0; t < 4; ++t) {
#pragma unroll
            for (int sub = 0; sub < 2; ++sub) {
                int lr = lr0 + t * 16 + sub * 8;
                const float* kr = kcs + lr * 4;
#pragma unroll
                for (int jj = 0; jj < 4; ++jj) {
                    int lcA = lc0 + jj * 8;           // d = lcA>>5, h = lcA&31
                    int lcB = lcA + 32;
                    float dA = kr[lcA >> 5], dB = kr[lcB >> 5];
                    float bA = bias[n0 + lcA], bA1 = bias[n0 + lcA + 1];
                    float bB = bias[n0 + lcB], bB1 = bias[n0 + lcB + 1];
                    float p0 = dA * (acc[t][jj][2 * sub] + bA)
                             + dB * (acc[t][jj + 4][2 * sub] + bB);
                    float p1 = dA * (acc[t][jj][2 * sub + 1] + bA1)
                             + dB * (acc[t][jj + 4][2 * sub + 1] + bB1);
                    int h = lcA & 31;
                    atomicAdd(&salign[lr * 32 + h],     p0);
                    atomicAdd(&salign[lr * 32 + h + 1], p1);
                }
            }
        }
        __syncthreads();
        {
            float* dst = C + ((size_t)(m0 + tid) * NTILES + blockIdx.x) * H_DIM;
            const float* src = salign + tid * 32;
#pragma unroll
            for (int i = 0; i < 8; ++i)
                *(float4*)(dst + i * 4) = *(const float4*)(src + i * 4);
        }
        return;
    }

    if (MODE == 3) {
        // ---- split-K partial store: no bias ----
        float* Cp = C + (size_t)blockIdx.z * ((size_t)S_DIM * D_DIM);
#pragma unroll
        for (int t = 0; t < 4; ++t) {
            int row0 = m0 + lr0 + t * 16;
#pragma unroll
            for (int j = 0; j < 8; ++j) {
                int col = n0 + lc0 + j * 8;
                *(float2*)(Cp + (size_t)row0 * ldC + col)
                    = make_float2(acc[t][j][0], acc[t][j][1]);
                *(float2*)(Cp + (size_t)(row0 + 8) * ldC + col)
                    = make_float2(acc[t][j][2], acc[t][j][3]);
            }
        }
        return;
    }

    // ---- MODE 2 epilogue ----
    const int rbase = m0 + lr0;
    const int cbase = n0 + lc0;
#pragma unroll
    for (int t = 0; t < 4; ++t) {
        int row0 = rbase + t * 16;
#pragma unroll
        for (int j = 0; j < 8; ++j) {
            int col = cbase + j * 8;
            float b0 = bias[col], b1 = bias[col + 1];
            float2 v0 = make_float2(acc[t][j][0] + b0, acc[t][j][1] + b1);
            float2 v1 = make_float2(acc[t][j][2] + b0, acc[t][j][3] + b1);
            {
                int h = col & 31;
                const float* w0 = aux + (size_t)row0 * H_DIM;
                const float* w1 = aux + (size_t)(row0 + 8) * H_DIM;
                v0.x *= w0[h]; v0.y *= w0[h + 1];
                v1.x *= w1[h]; v1.y *= w1[h + 1];
            }
            *(float2*)(C + (size_t)row0 * ldC + col)       = v0;
            *(float2*)(C + (size_t)(row0 + 8) * ldC + col) = v1;
        }
    }
}

// ---------------------------------------------------------------------------
// reduce partials + mask + softmax -> Wt.  One warp per row s.
// ---------------------------------------------------------------------------
__global__ void softmax_kernel(const float* __restrict__ pal,
                               const int* __restrict__ mask,
                               float* __restrict__ Wt)
{
    const int warp = threadIdx.x >> 5;
    const int h    = threadIdx.x & 31;
    const int s    = blockIdx.x * (blockDim.x >> 5) + warp;

    const float* p = pal + (size_t)s * NTILES * H_DIM;
    float acc = 0.f;
#pragma unroll 8
    for (int t = 0; t < NTILES; ++t)
        acc += p[t * H_DIM + h];

    acc *= (1.0f / 64.0f);                          // SCALE = sqrt(4096)
    if (mask[(size_t)s * H_DIM + h] == 0) acc = 1e-20f;

    float mx = acc;
#pragma unroll
    for (int o = 16; o > 0; o >>= 1) mx = fmaxf(mx, __shfl_xor_sync(0xffffffffu, mx, o));
    float e = __expf(acc - mx);
    float sum = e;
#pragma unroll
    for (int o = 16; o > 0; o >>= 1) sum += __shfl_xor_sync(0xffffffffu, sum, o);

    Wt[(size_t)s * H_DIM + h] = e / sum;
}

// ---------------------------------------------------------------------------
// Launch — R12 schedule: weight conversions off-path on side streams.
// ---------------------------------------------------------------------------
extern "C" void kernel_launch(void* const* d_in, const int* in_sizes, int n_in,
                              void* d_out, int out_size)
{
    (void)in_sizes; (void)n_in; (void)out_size;

    const float* x    = (const float*)d_in[0];
    const float* Wq   = (const float*)d_in[1];
    const float* bq   = (const float*)d_in[2];
    const float* Wk   = (const float*)d_in[3];
    const float* bk   = (const float*)d_in[4];
    const float* Wv   = (const float*)d_in[5];
    const float* bv   = (const float*)d_in[6];
    const int*   mask = (const int*)d_in[7];
    float* out = (float*)d_out;

    __half *xh, *wq, *wv, *wk;
    float *bkc, *Kc4p, *palp, *Wtp;
    cudaGetSymbolAddress((void**)&xh, g_x);
    cudaGetSymbolAddress((void**)&wq, g_wq);
    cudaGetSymbolAddress((void**)&wv, g_wv);
    cudaGetSymbolAddress((void**)&wk, g_wk);
    cudaGetSymbolAddress((void**)&bkc, g_bkc);
    cudaGetSymbolAddress((void**)&Kc4p, g_Kc4);
    cudaGetSymbolAddress((void**)&palp, g_pal);
    cudaGetSymbolAddress((void**)&Wtp, g_Wt);

    cudaFuncSetAttribute(gemm_mma_fp16<1>, cudaFuncAttributeMaxDynamicSharedMemorySize, SMEM_TOTAL);
    cudaFuncSetAttribute(gemm_mma_fp16<2>, cudaFuncAttributeMaxDynamicSharedMemorySize, SMEM_TOTAL);
    cudaFuncSetAttribute(gemm_mma_fp16<3>, cudaFuncAttributeMaxDynamicSharedMemorySize, SMEM_TOTAL);

    static cudaStream_t s2 = nullptr, s3 = nullptr, s4 = nullptr;
    static cudaEvent_t evRoot = nullptr, evWq = nullptr, evWv = nullptr, evWk = nullptr;
    if (!s2) {
        cudaStreamCreateWithFlags(&s2, cudaStreamNonBlocking);
        cudaStreamCreateWithFlags(&s3, cudaStreamNonBlocking);
        cudaStreamCreateWithFlags(&s4, cudaStreamNonBlocking);
        cudaEventCreateWithFlags(&evRoot, cudaEventDisableTiming);
        cudaEventCreateWithFlags(&evWq, cudaEventDisableTiming);
        cudaEventCreateWithFlags(&evWv, cudaEventDisableTiming);
        cudaEventCreateWithFlags(&evWk, cudaEventDisableTiming);
    }

    // fork side streams from the main (capture) stream
    cudaEventRecord(evRoot, 0);
    cudaStreamWaitEvent(s2, evRoot, 0);
    cudaStreamWaitEvent(s3, evRoot, 0);
    cudaStreamWaitEvent(s4, evRoot, 0);

    int n4x = (S_DIM * E_DIM) / 4;
    int n4w = (E_DIM * E_DIM) / 4;

    // critical path: x conversion on the main stream
    cvt_kernel<<<n4x / 256, 256>>>((const float4*)x, (__half2*)xh, n4x);
    // off-path: weight conversions on side streams
    cvt_kernel<<<n4w / 256, 256, 0, s2>>>((const float4*)Wq, (__half2*)wq, n4w);
    cudaEventRecord(evWq, s2);
    cvt_kernel<<<n4w / 256, 256, 0, s3>>>((const float4*)Wv, (__half2*)wv, n4w);
    cudaEventRecord(evWv, s3);
    gather_wk_kernel<<<(D_DIM * E_DIM / 4) / 256, 256, 0, s4>>>(Wk, bk, wk, bkc);
    cudaEventRecord(evWk, s4);

    // Kc split-K partials (needs x + Wk)
    cudaStreamWaitEvent(0, evWk, 0);
    gemm_mma_fp16<3><<<dim3(1, S_DIM / 128, KSPLIT), 128, SMEM_TOTAL>>>(xh, wk, bkc, Kc4p, D_DIM, nullptr);
    // Q GEMM with fused align epilogue (needs Wq + Kc partials)
    cudaStreamWaitEvent(0, evWq, 0);
    gemm_mma_fp16<1><<<dim3(E_DIM / 128, S_DIM / 128), 128, SMEM_TOTAL>>>(xh, wq, bq, palp, 0, nullptr);
    // reduce + mask + softmax
    softmax_kernel<<<S_DIM / 8, 256>>>(palp, mask, Wtp);
    // V GEMM (needs Wv + Wt)
    cudaStreamWaitEvent(0, evWv, 0);
    gemm_mma_fp16<2><<<dim3(E_DIM / 128, S_DIM / 128), 128, SMEM_TOTAL>>>(xh, wv, bv, out, E_DIM, Wtp);
}